// round 15
// baseline (speedup 1.0000x reference)
#include <cuda_runtime.h>
#include <math.h>

#define BATCH 16384
#define KNN 5

typedef unsigned long long u64;

// ---------------- scratch ----------------
__device__ float g_h1[BATCH * 20 * 300];
__device__ float g_h2[BATCH * 20 * 100];
__device__ float g_C[3 * 400];
__device__ float g_M[3 * 400];

// ---------------- packed f32x2 helpers ----------------
__device__ __forceinline__ u64 pack2(float lo, float hi) {
    u64 r;
    asm("mov.b64 %0, {%1, %2};" : "=l"(r) : "f"(lo), "f"(hi));
    return r;
}
__device__ __forceinline__ void unpack2(float& lo, float& hi, u64 v) {
    asm("mov.b64 {%0, %1}, %2;" : "=f"(lo), "=f"(hi) : "l"(v));
}
__device__ __forceinline__ u64 fma2(u64 a, u64 b, u64 c) {
    u64 d;
    asm("fma.rn.f32x2 %0, %1, %2, %3;" : "=l"(d) : "l"(a), "l"(b), "l"(c));
    return d;
}

// ---------------- tiny kernels ----------------
__global__ void zero_counts_kernel(float* C) {
    int t = blockIdx.x * blockDim.x + threadIdx.x;
    if (t < 1200) C[t] = 0.f;
}

__global__ void build_M_kernel(const float* __restrict__ C, float* __restrict__ M) {
    __shared__ float dinv[20];
    int t = threadIdx.x;
    if (t < 20) {
        float s = 1.f;
#pragma unroll
        for (int u = 0; u < 20; u++) s += C[t * 20 + u];
        dinv[t] = 1.f / sqrtf(s);
    }
    __syncthreads();
    for (int i = t; i < 400; i += blockDim.x) {
        int v = i / 20, u = i % 20;
        float m = dinv[v] * C[i] * dinv[u];
        if (v == u) m += dinv[v] * dinv[v];
        M[i] = m;
    }
}

// ---------------- block-local kNN + count accumulation (scalar, R6) ----------------
template<int NS, int DIM, int STRIDE>
__device__ void knn_accumulate(const float* __restrict__ sh,
                               float* __restrict__ sdq, float* __restrict__ sd2,
                               float* __restrict__ sC, float* __restrict__ gC,
                               int tid) {
    constexpr int ROWS = NS * 20;
    for (int i = tid; i < 400; i += 256) sC[i] = 0.f;
    for (int t = tid; t < ROWS; t += 256) {
        const float* hp = sh + t * STRIDE;
        float s = 0.f;
        for (int d = 0; d < DIM; d++) { float h = hp[d]; s += h * h; }
        sdq[t] = s;
    }
    __syncthreads();
    for (int t = tid; t < NS * 190; t += 256) {
        int s = t / 190, rem = t % 190;
        int i = 0;
        while (rem >= 19 - i) { rem -= 19 - i; i++; }
        int j = i + 1 + rem;
        const float* ha = sh + (s * 20 + i) * STRIDE;
        const float* hb = sh + (s * 20 + j) * STRIDE;
        float dot = 0.f;
        for (int d = 0; d < DIM; d++) dot += ha[d] * hb[d];
        float d2 = sdq[s * 20 + i] + sdq[s * 20 + j] - 2.f * dot;
        sd2[s * 400 + i * 20 + j] = d2;
        sd2[s * 400 + j * 20 + i] = d2;
    }
    __syncthreads();
    for (int t = tid; t < ROWS; t += 256) {
        int s = t / 20, v = t % 20;
        const float* row = sd2 + s * 400 + v * 20;
        float bv[KNN]; int bi[KNN];
#pragma unroll
        for (int k = 0; k < KNN; k++) { bv[k] = 3.4e38f; bi[k] = 99; }
        for (int u = 0; u < 20; u++) {
            if (u == v) continue;
            float d = row[u];
            if (d < bv[KNN - 1]) {
                bv[KNN - 1] = d; bi[KNN - 1] = u;
#pragma unroll
                for (int k = KNN - 1; k > 0; k--) {
                    if (bv[k] < bv[k - 1]) {
                        float tv = bv[k]; bv[k] = bv[k - 1]; bv[k - 1] = tv;
                        int ti = bi[k]; bi[k] = bi[k - 1]; bi[k - 1] = ti;
                    }
                }
            }
        }
#pragma unroll
        for (int k = 0; k < KNN; k++)
            atomicAdd(&sC[bi[k] * 20 + v], 1.f);   // C[nbr][src]
    }
    __syncthreads();
    for (int i = tid; i < 400; i += 256) {
        float c = sC[i];
        if (c != 0.f) atomicAdd(&gC[i], c);
    }
}

// ---------------- standalone kNN kernel (R6: odd stride DIM+1, scalar) ----------------
template<int NS, int DIM>
__global__ __launch_bounds__(256) void knn_kernel(const float* __restrict__ h,
                                                  float* __restrict__ gC) {
    constexpr int DIMP = DIM + 1;
    constexpr int ROWS = NS * 20;
    extern __shared__ float sm[];
    float* sh  = sm;
    float* sdq = sh + ROWS * DIMP;
    float* sd2 = sdq + ROWS;
    float* sC  = sd2 + NS * 400;
    int tid = threadIdx.x;
    size_t samp0 = (size_t)blockIdx.x * NS;
    const float* gx = h + samp0 * 20 * DIM;
    for (int idx = tid; idx < ROWS * DIM; idx += 256) {
        int r = idx / DIM, d = idx - r * DIM;
        sh[r * DIMP + d] = gx[idx];
    }
    __syncthreads();
    knn_accumulate<NS, DIM, DIMP>(sh, sdq, sd2, sC, gC, tid);
}

// ---------------- layer1 (R12 split-K, measured ~822us) ----------------
__global__ __launch_bounds__(256, 2) void layer1_kernel(
    const float* __restrict__ hin, const float* __restrict__ W,
    const float* __restrict__ bias, const float* __restrict__ Mptr,
    float* __restrict__ hout) {
    constexpr int DIN = 128, DOUT = 300, NS = 4;
    constexpr int ROWS = 80;
    constexpr int RP = 84;
    constexpr int WSTR = 133;
    constexpr int WCH = 128;
    extern __shared__ float sm[];
    float* sM  = sm;                      // 400
    float* sb  = sM + 400;                // 304
    float* shT = sb + 304;                // DIN*RP = 10752
    float* sW  = shT + DIN * RP;          // WCH*WSTR = 17024 (reused as scratch)
    u64* scratch = reinterpret_cast<u64*>(sW);

    int tid = threadIdx.x, lane = tid & 31, wy = tid >> 5;
    size_t samp0 = (size_t)blockIdx.x * NS;

    for (int i = tid; i < 400; i += 256) sM[i] = Mptr[i];
    for (int i = tid; i < DOUT; i += 256) sb[i] = bias[i];
    const float* gh = hin + samp0 * 20 * DIN;
    for (int idx = tid; idx < ROWS * DIN; idx += 256) {
        int r = idx >> 7, d = idx & 127;
        shT[d * RP + r] = gh[idx];
    }
    __syncthreads();

    float Mr[20];
    {
        int v = lane < 20 ? lane : 0;
#pragma unroll
        for (int u = 0; u < 20; u++) Mr[u] = sM[v * 20 + u];
    }
    for (int col = wy; col < NS * DIN; col += 8) {
        int s = col >> 7, d = col & 127;
        float* c0 = shT + d * RP + s * 20;
        float a = 0.f;
#pragma unroll
        for (int u = 0; u < 20; u++) a += Mr[u] * c0[u];
        __syncwarp();
        if (lane < 20) c0[lane] = a;
        __syncwarp();
    }
    __syncthreads();

    int s = wy >> 1, dh = wy & 1;
    int dbeg = dh * 64, dend = dbeg + 64;
    float* go = hout + samp0 * 20 * DOUT;

    for (int cb = 0; cb < DOUT; cb += WCH) {
        __syncthreads();
        for (int idx = tid; idx < WCH * DIN; idx += 256) {
            int c = idx >> 7, d = idx & 127;
            int gc = cb + c;
            sW[c * WSTR + d] = (gc < DOUT) ? W[(size_t)gc * DIN + d] : 0.f;
        }
        __syncthreads();

        u64 acc2[10][4];
#pragma unroll
        for (int i = 0; i < 10; i++)
#pragma unroll
            for (int k = 0; k < 4; k++) acc2[i][k] = 0ull;

        const float* wb0 = sW + lane * WSTR;
        const float* wb1 = sW + (lane + 32) * WSTR;
        const float* wb2 = sW + (lane + 64) * WSTR;
        const float* wb3 = sW + (lane + 96) * WSTR;
        for (int d = dbeg; d < dend; d++) {
            const ulonglong2* ap = reinterpret_cast<const ulonglong2*>(shT + d * RP + s * 20);
            ulonglong2 p0 = ap[0], p1 = ap[1], p2 = ap[2], p3 = ap[3], p4 = ap[4];
            u64 a2[10] = {p0.x, p0.y, p1.x, p1.y, p2.x, p2.y, p3.x, p3.y, p4.x, p4.y};
            float w0 = wb0[d], w1 = wb1[d], w2 = wb2[d], w3 = wb3[d];
            u64 wp0 = pack2(w0, w0), wp1 = pack2(w1, w1);
            u64 wp2 = pack2(w2, w2), wp3 = pack2(w3, w3);
#pragma unroll
            for (int i = 0; i < 10; i++) {
                u64 a = a2[i];
                acc2[i][0] = fma2(a, wp0, acc2[i][0]);
                acc2[i][1] = fma2(a, wp1, acc2[i][1]);
                acc2[i][2] = fma2(a, wp2, acc2[i][2]);
                acc2[i][3] = fma2(a, wp3, acc2[i][3]);
            }
        }
        __syncthreads();

        if (dh == 1) {
            u64* dst = scratch + s * 1312 + lane * 41;
#pragma unroll
            for (int i = 0; i < 10; i++)
#pragma unroll
                for (int k = 0; k < 4; k++)
                    dst[i * 4 + k] = acc2[i][k];
        }
        __syncthreads();

        if (dh == 0) {
            const u64* src = scratch + s * 1312 + lane * 41;
#pragma unroll
            for (int k = 0; k < 4; k++) {
                int c = cb + lane + 32 * k;
                if (c < DOUT) {
                    float bc = sb[c];
#pragma unroll
                    for (int i = 0; i < 10; i++) {
                        float lo, hi, lo2, hi2;
                        unpack2(lo, hi, acc2[i][k]);
                        unpack2(lo2, hi2, src[i * 4 + k]);
                        int r0 = s * 20 + 2 * i;
                        go[(size_t)r0 * DOUT + c]       = fmaxf(lo + lo2 + bc, 0.f);
                        go[(size_t)(r0 + 1) * DOUT + c] = fmaxf(hi + hi2 + bc, 0.f);
                    }
                }
            }
        }
    }
}

// ---------------- layer2 (R6 GEMM) + FUSED knn100 on in-smem h2 ----------------
// NS=4, 8 warps x 10 rows (5 u64 pairs), 4 col slots per thread.
// After h2 is finalized in sz, runs knn_accumulate on it using the dead sWc
// buffer as scratch (sdq/sd2/sC = 2080 floats <= 10500), eliminating the
// standalone knn100 kernel.
__global__ __launch_bounds__(256, 2) void layer2_kernel(
    const float* __restrict__ hin, const float* __restrict__ W,
    const float* __restrict__ bias, const float* __restrict__ Mptr,
    float* __restrict__ hout, float* __restrict__ Cnext) {
    constexpr int DIN = 300, DOUT = 100, NS = 4;
    constexpr int ROWS = 80;
    constexpr int ROWSP = 82;
    constexpr int DCH = 100;
    constexpr int WST = 105;           // mod 32 = 9, conflict-free
    constexpr int SZP = 101;
    extern __shared__ float sm[];
    float* sM  = sm;                       // 400
    float* sb  = sM + 400;                 // 104
    float* shT = sb + 104;                 // DCH*ROWSP = 8200
    float* sWc = shT + DCH * ROWSP;        // DOUT*WST = 10500
    float* sz  = sWc + DOUT * WST;         // ROWS*SZP = 8080

    int tid = threadIdx.x, lane = tid & 31, wy = tid >> 5;
    size_t samp0 = (size_t)blockIdx.x * NS;

    for (int i = tid; i < 400; i += 256) sM[i] = Mptr[i];
    for (int i = tid; i < DOUT; i += 256) sb[i] = bias[i];

    u64 acc2[5][4];
#pragma unroll
    for (int i = 0; i < 5; i++)
#pragma unroll
        for (int k = 0; k < 4; k++) acc2[i][k] = 0ull;

    const u64* aBase = reinterpret_cast<const u64*>(shT);
    int rowHalf = wy * 5;
    const float* ghrow = hin + samp0 * 20 * DIN;

    for (int dc = 0; dc < DIN; dc += DCH) {
        __syncthreads();
        for (int idx = tid; idx < ROWS * DCH; idx += 256) {
            int r = idx / DCH, j = idx - r * DCH;
            shT[j * ROWSP + r] = ghrow[(size_t)r * DIN + dc + j];
        }
        for (int idx = tid; idx < DOUT * DCH; idx += 256) {
            int o = idx / DCH, j = idx - o * DCH;
            sWc[o * WST + j] = W[(size_t)o * DIN + dc + j];
        }
        __syncthreads();
#pragma unroll 2
        for (int j = 0; j < DCH; j++) {
            const u64* ar = aBase + j * (ROWSP / 2) + rowHalf;
            float w0 = sWc[lane * WST + j];
            float w1 = sWc[(lane + 32) * WST + j];
            float w2 = sWc[(lane + 64) * WST + j];
            float w3 = (lane < 4) ? sWc[(lane + 96) * WST + j] : 0.f;
            u64 wp0 = pack2(w0, w0);
            u64 wp1 = pack2(w1, w1);
            u64 wp2 = pack2(w2, w2);
            u64 wp3 = pack2(w3, w3);
#pragma unroll
            for (int i = 0; i < 5; i++) {
                u64 a2 = ar[i];
                acc2[i][0] = fma2(a2, wp0, acc2[i][0]);
                acc2[i][1] = fma2(a2, wp1, acc2[i][1]);
                acc2[i][2] = fma2(a2, wp2, acc2[i][2]);
                acc2[i][3] = fma2(a2, wp3, acc2[i][3]);
            }
        }
    }
    __syncthreads();

    // write z to smem
#pragma unroll
    for (int k = 0; k < 4; k++) {
        int c = lane + 32 * k;
        if (c < DOUT) {
#pragma unroll
            for (int i = 0; i < 5; i++) {
                float lo, hi;
                unpack2(lo, hi, acc2[i][k]);
                int r0 = wy * 10 + 2 * i;
                sz[r0 * SZP + c]       = lo;
                sz[(r0 + 1) * SZP + c] = hi;
            }
        }
    }
    __syncthreads();

    // h2 = relu(M z + b2) in place
    float Mr[20];
    {
        int v = lane < 20 ? lane : 0;
#pragma unroll
        for (int u = 0; u < 20; u++) Mr[u] = sM[v * 20 + u];
    }
    for (int t = wy; t < NS * DOUT; t += 8) {
        int ss = t / DOUT, c = t - ss * DOUT;
        float* zc = sz + (ss * 20) * SZP + c;
        float a = 0.f;
#pragma unroll
        for (int u = 0; u < 20; u++) a += Mr[u] * zc[u * SZP];
        float h = fmaxf(a + sb[c], 0.f);
        __syncwarp();
        if (lane < 20) zc[lane * SZP] = h;
        __syncwarp();
    }
    __syncthreads();

    // store h2 to gmem (needed by final_kernel)
    float* go = hout + samp0 * 20 * DOUT;
    for (int idx = tid; idx < ROWS * DOUT; idx += 256) {
        int r = idx / DOUT, c = idx - r * DOUT;
        go[idx] = sz[r * SZP + c];
    }

    // fused knn100 on in-smem h2; scratch aliases the dead sWc buffer
    {
        float* sdq = sWc;            // 80
        float* sd2 = sWc + 80;       // 1600
        float* sC  = sWc + 1680;     // 400  (total 2080 <= 10500)
        knn_accumulate<NS, DOUT, SZP>(sz, sdq, sd2, sC, Cnext, tid);
    }
}

// ---------------- layer3 + flatten + FC head + softmax (R6 version) ----------------
#define W4STR 1005   // mod 32 = 13 -> conflict-free jl-strided reads
__global__ __launch_bounds__(256) void final_kernel(
    const float* __restrict__ hin, const float* __restrict__ W3, const float* __restrict__ b3,
    const float* __restrict__ Mptr, const float* __restrict__ W4, const float* __restrict__ b4,
    const float* __restrict__ W5, const float* __restrict__ b5, float* __restrict__ out) {
    constexpr int DIN = 100, DINP = 101, DOUT = 50, DOUTP = 51;
    constexpr int NS = 8, ROWS = 160, WCH = 64;
    extern __shared__ float sm[];
    float* sM  = sm;                 // 400
    float* sb3 = sM + 400;           // 64 (padded)
    float* sh  = sb3 + 64;           // 160*101
    float* sz  = sh + ROWS * DINP;   // 160*51
    float* sW  = sz + ROWS * DOUTP;  // 64*101
    float* sW4 = sW + WCH * DINP;    // 16*W4STR
    float* sh4 = sW4 + 16 * W4STR;   // 8*100
    float* ph  = sh4 + NS * 100;     // 256
    float* sW5 = ph + 256;           // 300
    float* sb5 = sW5 + 300;          // 4
    float* sb4 = sb5 + 4;            // 100

    int tid = threadIdx.x;
    size_t samp0 = (size_t)blockIdx.x * NS;

    for (int i = tid; i < 400; i += 256) sM[i] = Mptr[i];
    for (int i = tid; i < DOUT; i += 256) sb3[i] = b3[i];
    for (int i = tid; i < 300; i += 256) sW5[i] = W5[i];
    for (int i = tid; i < 100; i += 256) sb4[i] = b4[i];
    if (tid < 3) sb5[tid] = b5[tid];
    const float* gh = hin + samp0 * 20 * DIN;
    for (int idx = tid; idx < ROWS * DIN; idx += 256) {
        int r = idx / DIN, d = idx - r * DIN;
        sh[r * DINP + d] = gh[idx];
    }
    for (int idx = tid; idx < WCH * DIN; idx += 256) {
        int c = idx / DIN, d = idx - c * DIN;
        sW[c * DINP + d] = (c < DOUT) ? W3[c * DIN + d] : 0.f;
    }
    __syncthreads();

    int lane = tid & 31, wid = tid >> 5;
    float Mr[20];
    {
        int v = lane < 20 ? lane : 0;
#pragma unroll
        for (int u = 0; u < 20; u++) Mr[u] = sM[v * 20 + u];
    }

    // GEMM z = h @ W3^T : 160 rows, 10 rows per ty, strided cols
    int ty = tid >> 4, tx = tid & 15;
    {
        float acc[10][4];
#pragma unroll
        for (int i = 0; i < 10; i++)
#pragma unroll
            for (int k = 0; k < 4; k++) acc[i][k] = 0.f;
        const float* shp = sh + (ty * 10) * DINP;
        const float* sw0 = sW + tx * DINP;
        for (int d = 0; d < DIN; d++) {
            float a[10];
#pragma unroll
            for (int i = 0; i < 10; i++) a[i] = shp[i * DINP + d];
#pragma unroll
            for (int k = 0; k < 4; k++) {
                float w = sw0[k * 16 * DINP + d];
#pragma unroll
                for (int i = 0; i < 10; i++) acc[i][k] += a[i] * w;
            }
        }
#pragma unroll
        for (int k = 0; k < 4; k++) {
            int gc = tx + k * 16;
            if (gc < DOUT) {
#pragma unroll
                for (int i = 0; i < 10; i++)
                    sz[(ty * 10 + i) * DOUTP + gc] = acc[i][k];
            }
        }
    }
    __syncthreads();

    // h3 = relu(M z + b3) in place
    for (int col = wid; col < NS * DOUT; col += 8) {
        int s = col / DOUT, o = col - s * DOUT;
        float* zc = sz + (s * 20) * DOUTP + o;
        float a = 0.f;
#pragma unroll
        for (int u = 0; u < 20; u++) a += Mr[u] * zc[u * DOUTP];
        float h = fmaxf(a + sb3[o], 0.f);
        __syncwarp();
        if (lane < 20) zc[lane * DOUTP] = h;
        __syncwarp();
    }
    __syncthreads();

    // head: h4 = relu(flat @ W4^T + b4), W4 streamed in 16-row smem chunks (guarded).
    for (int jc = 0; jc < 100; jc += 16) {
        __syncthreads();
        for (int idx = tid; idx < 16000; idx += 256) {
            int rloc = idx / 1000, cloc = idx - rloc * 1000;
            int r = jc + rloc;
            sW4[rloc * W4STR + cloc] = (r < 100) ? W4[(size_t)r * 1000 + cloc] : 0.f;
        }
        __syncthreads();
        int task = tid & 127;
        int half = tid >> 7;
        int s = task >> 4, jl = task & 15;
        const float* zrow = sz + (s * 20) * DOUTP;
        const float* wrow = sW4 + jl * W4STR;
        float p = 0.f;
        int v0 = half * 10;
        for (int v = v0; v < v0 + 10; v++) {
            const float* zp = zrow + v * DOUTP;
            const float* wp = wrow + v * 50;
#pragma unroll 10
            for (int f = 0; f < 50; f++) p += zp[f] * wp[f];
        }
        ph[tid] = p;
        __syncthreads();
        if (tid < 128) {
            int s2 = tid >> 4, jl2 = tid & 15;
            if (jc + jl2 < 100) {
                float hv = ph[tid] + ph[tid + 128] + sb4[jc + jl2];
                sh4[s2 * 100 + jc + jl2] = fmaxf(hv, 0.f);
            }
        }
    }
    __syncthreads();

    // logits + softmax
    if (tid < NS) {
        const float* hp = sh4 + tid * 100;
        float l[3];
#pragma unroll
        for (int c = 0; c < 3; c++) {
            float a = sb5[c];
            for (int j = 0; j < 100; j++) a += hp[j] * sW5[c * 100 + j];
            l[c] = a;
        }
        float mx = fmaxf(l[0], fmaxf(l[1], l[2]));
        float e0 = expf(l[0] - mx), e1 = expf(l[1] - mx), e2 = expf(l[2] - mx);
        float inv = 1.f / (e0 + e1 + e2);
        size_t ob = (samp0 + (size_t)tid) * 3;
        out[ob + 0] = e0 * inv;
        out[ob + 1] = e1 * inv;
        out[ob + 2] = e2 * inv;
    }
}

// ---------------- host ----------------
extern "C" void kernel_launch(void* const* d_in, const int* in_sizes, int n_in,
                              void* d_out, int out_size) {
    const float *x = 0, *W1 = 0, *b1 = 0, *W2 = 0, *b2 = 0, *W3 = 0, *b3 = 0,
                *W4 = 0, *b4 = 0, *W5 = 0, *b5 = 0;
    int idx_x = -1;
    for (int i = 0; i < n_in; i++) if (in_sizes[i] == 41943040) { idx_x = i; break; }
    if (idx_x == 0 || idx_x < 0) {
        x  = (const float*)d_in[0];
        W1 = (const float*)d_in[1];  b1 = (const float*)d_in[2];
        W2 = (const float*)d_in[3];  b2 = (const float*)d_in[4];
        W3 = (const float*)d_in[5];  b3 = (const float*)d_in[6];
        W4 = (const float*)d_in[7];  b4 = (const float*)d_in[8];
        W5 = (const float*)d_in[9];  b5 = (const float*)d_in[10];
    } else {
        int i300_a = -1, i300_b = -1, i100_a = -1, i100_b = -1;
        for (int i = 0; i < n_in; i++) {
            int s = in_sizes[i];
            if (s == 38400)  W1 = (const float*)d_in[i];
            else if (s == 30000) W2 = (const float*)d_in[i];
            else if (s == 5000)  W3 = (const float*)d_in[i];
            else if (s == 100000) W4 = (const float*)d_in[i];
            else if (s == 50)    b3 = (const float*)d_in[i];
            else if (s == 3)     b5 = (const float*)d_in[i];
            else if (s == 41943040) x = (const float*)d_in[i];
            else if (s == 300) { if (i300_a < 0) i300_a = i; else i300_b = i; }
            else if (s == 100) { if (i100_a < 0) i100_a = i; else i100_b = i; }
        }
        W5 = (const float*)d_in[i300_a];  b1 = (const float*)d_in[i300_b];
        b2 = (const float*)d_in[i100_a];  b4 = (const float*)d_in[i100_b];
    }
    float* out = (float*)d_out;

    float *pC = 0, *pM = 0, *ph1 = 0, *ph2 = 0;
    cudaGetSymbolAddress((void**)&pC, g_C);
    cudaGetSymbolAddress((void**)&pM, g_M);
    cudaGetSymbolAddress((void**)&ph1, g_h1);
    cudaGetSymbolAddress((void**)&ph2, g_h2);

    size_t sm_l1  = sizeof(float) * (size_t)(400 + 304 + 128 * 84 + 128 * 133);
    size_t sm_l2  = sizeof(float) * (size_t)(400 + 104 + 100 * 82 + 100 * 105 + 80 * 101);
    size_t sm_k128 = sizeof(float) * (size_t)(80 * 129 + 80 + 4 * 400 + 400);
    size_t sm_k300 = sizeof(float) * (size_t)(80 * 301 + 80 + 4 * 400 + 400);
    size_t sm_fin = sizeof(float) * (size_t)(400 + 64 + 160 * 101 + 160 * 51 +
                                             64 * 101 + 16 * W4STR + 800 + 256 + 300 + 4 + 100);

    cudaFuncSetAttribute(layer1_kernel, cudaFuncAttributeMaxDynamicSharedMemorySize, (int)sm_l1);
    cudaFuncSetAttribute(layer2_kernel, cudaFuncAttributeMaxDynamicSharedMemorySize, (int)sm_l2);
    cudaFuncSetAttribute((knn_kernel<4, 128>), cudaFuncAttributeMaxDynamicSharedMemorySize, (int)sm_k128);
    cudaFuncSetAttribute((knn_kernel<4, 300>), cudaFuncAttributeMaxDynamicSharedMemorySize, (int)sm_k300);
    cudaFuncSetAttribute(final_kernel, cudaFuncAttributeMaxDynamicSharedMemorySize, (int)sm_fin);

    zero_counts_kernel<<<5, 256>>>(pC);
    knn_kernel<4, 128><<<BATCH / 4, 256, sm_k128>>>(x, pC);
    build_M_kernel<<<1, 64>>>(pC, pM);
    layer1_kernel<<<BATCH / 4, 256, sm_l1>>>(x, W1, b1, pM, ph1);
    knn_kernel<4, 300><<<BATCH / 4, 256, sm_k300>>>(ph1, pC + 400);
    build_M_kernel<<<1, 64>>>(pC + 400, pM + 400);
    layer2_kernel<<<BATCH / 4, 256, sm_l2>>>(ph1, W2, b2, pM + 400, ph2, pC + 800);
    build_M_kernel<<<1, 64>>>(pC + 800, pM + 800);
    final_kernel<<<BATCH / 8, 256, sm_fin>>>(ph2, W3, b3, pM + 800, W4, b4, W5, b5, out);
}

// round 16
// speedup vs baseline: 1.1071x; 1.1071x over previous
#include <cuda_runtime.h>
#include <math.h>

#define BATCH 16384
#define KNN 5

typedef unsigned long long u64;

// ---------------- scratch ----------------
__device__ float g_h1[BATCH * 20 * 300];
__device__ float g_h2[BATCH * 20 * 100];
__device__ float g_C[3 * 400];
__device__ float g_M[3 * 400];

// ---------------- packed f32x2 helpers ----------------
__device__ __forceinline__ u64 pack2(float lo, float hi) {
    u64 r;
    asm("mov.b64 %0, {%1, %2};" : "=l"(r) : "f"(lo), "f"(hi));
    return r;
}
__device__ __forceinline__ void unpack2(float& lo, float& hi, u64 v) {
    asm("mov.b64 {%0, %1}, %2;" : "=f"(lo), "=f"(hi) : "l"(v));
}
__device__ __forceinline__ u64 fma2(u64 a, u64 b, u64 c) {
    u64 d;
    asm("fma.rn.f32x2 %0, %1, %2, %3;" : "=l"(d) : "l"(a), "l"(b), "l"(c));
    return d;
}

// ---------------- tiny kernels ----------------
__global__ void zero_counts_kernel(float* C) {
    int t = blockIdx.x * blockDim.x + threadIdx.x;
    if (t < 1200) C[t] = 0.f;
}

__global__ void build_M_kernel(const float* __restrict__ C, float* __restrict__ M) {
    __shared__ float dinv[20];
    int t = threadIdx.x;
    if (t < 20) {
        float s = 1.f;
#pragma unroll
        for (int u = 0; u < 20; u++) s += C[t * 20 + u];
        dinv[t] = 1.f / sqrtf(s);
    }
    __syncthreads();
    for (int i = t; i < 400; i += blockDim.x) {
        int v = i / 20, u = i % 20;
        float m = dinv[v] * C[i] * dinv[u];
        if (v == u) m += dinv[v] * dinv[v];
        M[i] = m;
    }
}

// ---------------- block-local kNN + count accumulation (scalar, R6) ----------------
template<int NS, int DIM, int STRIDE>
__device__ void knn_accumulate(const float* __restrict__ sh,
                               float* __restrict__ sdq, float* __restrict__ sd2,
                               float* __restrict__ sC, float* __restrict__ gC,
                               int tid) {
    constexpr int ROWS = NS * 20;
    for (int i = tid; i < 400; i += 256) sC[i] = 0.f;
    for (int t = tid; t < ROWS; t += 256) {
        const float* hp = sh + t * STRIDE;
        float s = 0.f;
        for (int d = 0; d < DIM; d++) { float h = hp[d]; s += h * h; }
        sdq[t] = s;
    }
    __syncthreads();
    for (int t = tid; t < NS * 190; t += 256) {
        int s = t / 190, rem = t % 190;
        int i = 0;
        while (rem >= 19 - i) { rem -= 19 - i; i++; }
        int j = i + 1 + rem;
        const float* ha = sh + (s * 20 + i) * STRIDE;
        const float* hb = sh + (s * 20 + j) * STRIDE;
        float dot = 0.f;
        for (int d = 0; d < DIM; d++) dot += ha[d] * hb[d];
        float d2 = sdq[s * 20 + i] + sdq[s * 20 + j] - 2.f * dot;
        sd2[s * 400 + i * 20 + j] = d2;
        sd2[s * 400 + j * 20 + i] = d2;
    }
    __syncthreads();
    for (int t = tid; t < ROWS; t += 256) {
        int s = t / 20, v = t % 20;
        const float* row = sd2 + s * 400 + v * 20;
        float bv[KNN]; int bi[KNN];
#pragma unroll
        for (int k = 0; k < KNN; k++) { bv[k] = 3.4e38f; bi[k] = 99; }
        for (int u = 0; u < 20; u++) {
            if (u == v) continue;
            float d = row[u];
            if (d < bv[KNN - 1]) {
                bv[KNN - 1] = d; bi[KNN - 1] = u;
#pragma unroll
                for (int k = KNN - 1; k > 0; k--) {
                    if (bv[k] < bv[k - 1]) {
                        float tv = bv[k]; bv[k] = bv[k - 1]; bv[k - 1] = tv;
                        int ti = bi[k]; bi[k] = bi[k - 1]; bi[k - 1] = ti;
                    }
                }
            }
        }
#pragma unroll
        for (int k = 0; k < KNN; k++)
            atomicAdd(&sC[bi[k] * 20 + v], 1.f);   // C[nbr][src]
    }
    __syncthreads();
    for (int i = tid; i < 400; i += 256) {
        float c = sC[i];
        if (c != 0.f) atomicAdd(&gC[i], c);
    }
}

// ---------------- standalone kNN kernel (R6: odd stride DIM+1, scalar) ----------------
template<int NS, int DIM>
__global__ __launch_bounds__(256) void knn_kernel(const float* __restrict__ h,
                                                  float* __restrict__ gC) {
    constexpr int DIMP = DIM + 1;
    constexpr int ROWS = NS * 20;
    extern __shared__ float sm[];
    float* sh  = sm;
    float* sdq = sh + ROWS * DIMP;
    float* sd2 = sdq + ROWS;
    float* sC  = sd2 + NS * 400;
    int tid = threadIdx.x;
    size_t samp0 = (size_t)blockIdx.x * NS;
    const float* gx = h + samp0 * 20 * DIM;
    for (int idx = tid; idx < ROWS * DIM; idx += 256) {
        int r = idx / DIM, d = idx - r * DIM;
        sh[r * DIMP + d] = gx[idx];
    }
    __syncthreads();
    knn_accumulate<NS, DIM, DIMP>(sh, sdq, sd2, sC, gC, tid);
}

// ---------------- layer1 (R12 split-K, measured ~825us) ----------------
__global__ __launch_bounds__(256, 2) void layer1_kernel(
    const float* __restrict__ hin, const float* __restrict__ W,
    const float* __restrict__ bias, const float* __restrict__ Mptr,
    float* __restrict__ hout) {
    constexpr int DIN = 128, DOUT = 300, NS = 4;
    constexpr int ROWS = 80;
    constexpr int RP = 84;
    constexpr int WSTR = 133;
    constexpr int WCH = 128;
    extern __shared__ float sm[];
    float* sM  = sm;                      // 400
    float* sb  = sM + 400;                // 304
    float* shT = sb + 304;                // DIN*RP = 10752
    float* sW  = shT + DIN * RP;          // WCH*WSTR = 17024 (reused as scratch)
    u64* scratch = reinterpret_cast<u64*>(sW);

    int tid = threadIdx.x, lane = tid & 31, wy = tid >> 5;
    size_t samp0 = (size_t)blockIdx.x * NS;

    for (int i = tid; i < 400; i += 256) sM[i] = Mptr[i];
    for (int i = tid; i < DOUT; i += 256) sb[i] = bias[i];
    const float* gh = hin + samp0 * 20 * DIN;
    for (int idx = tid; idx < ROWS * DIN; idx += 256) {
        int r = idx >> 7, d = idx & 127;
        shT[d * RP + r] = gh[idx];
    }
    __syncthreads();

    float Mr[20];
    {
        int v = lane < 20 ? lane : 0;
#pragma unroll
        for (int u = 0; u < 20; u++) Mr[u] = sM[v * 20 + u];
    }
    for (int col = wy; col < NS * DIN; col += 8) {
        int s = col >> 7, d = col & 127;
        float* c0 = shT + d * RP + s * 20;
        float a = 0.f;
#pragma unroll
        for (int u = 0; u < 20; u++) a += Mr[u] * c0[u];
        __syncwarp();
        if (lane < 20) c0[lane] = a;
        __syncwarp();
    }
    __syncthreads();

    int s = wy >> 1, dh = wy & 1;
    int dbeg = dh * 64, dend = dbeg + 64;
    float* go = hout + samp0 * 20 * DOUT;

    for (int cb = 0; cb < DOUT; cb += WCH) {
        __syncthreads();
        for (int idx = tid; idx < WCH * DIN; idx += 256) {
            int c = idx >> 7, d = idx & 127;
            int gc = cb + c;
            sW[c * WSTR + d] = (gc < DOUT) ? W[(size_t)gc * DIN + d] : 0.f;
        }
        __syncthreads();

        u64 acc2[10][4];
#pragma unroll
        for (int i = 0; i < 10; i++)
#pragma unroll
            for (int k = 0; k < 4; k++) acc2[i][k] = 0ull;

        const float* wb0 = sW + lane * WSTR;
        const float* wb1 = sW + (lane + 32) * WSTR;
        const float* wb2 = sW + (lane + 64) * WSTR;
        const float* wb3 = sW + (lane + 96) * WSTR;
        for (int d = dbeg; d < dend; d++) {
            const ulonglong2* ap = reinterpret_cast<const ulonglong2*>(shT + d * RP + s * 20);
            ulonglong2 p0 = ap[0], p1 = ap[1], p2 = ap[2], p3 = ap[3], p4 = ap[4];
            u64 a2[10] = {p0.x, p0.y, p1.x, p1.y, p2.x, p2.y, p3.x, p3.y, p4.x, p4.y};
            float w0 = wb0[d], w1 = wb1[d], w2 = wb2[d], w3 = wb3[d];
            u64 wp0 = pack2(w0, w0), wp1 = pack2(w1, w1);
            u64 wp2 = pack2(w2, w2), wp3 = pack2(w3, w3);
#pragma unroll
            for (int i = 0; i < 10; i++) {
                u64 a = a2[i];
                acc2[i][0] = fma2(a, wp0, acc2[i][0]);
                acc2[i][1] = fma2(a, wp1, acc2[i][1]);
                acc2[i][2] = fma2(a, wp2, acc2[i][2]);
                acc2[i][3] = fma2(a, wp3, acc2[i][3]);
            }
        }
        __syncthreads();

        if (dh == 1) {
            u64* dst = scratch + s * 1312 + lane * 41;
#pragma unroll
            for (int i = 0; i < 10; i++)
#pragma unroll
                for (int k = 0; k < 4; k++)
                    dst[i * 4 + k] = acc2[i][k];
        }
        __syncthreads();

        if (dh == 0) {
            const u64* src = scratch + s * 1312 + lane * 41;
#pragma unroll
            for (int k = 0; k < 4; k++) {
                int c = cb + lane + 32 * k;
                if (c < DOUT) {
                    float bc = sb[c];
#pragma unroll
                    for (int i = 0; i < 10; i++) {
                        float lo, hi, lo2, hi2;
                        unpack2(lo, hi, acc2[i][k]);
                        unpack2(lo2, hi2, src[i * 4 + k]);
                        int r0 = s * 20 + 2 * i;
                        go[(size_t)r0 * DOUT + c]       = fmaxf(lo + lo2 + bc, 0.f);
                        go[(size_t)(r0 + 1) * DOUT + c] = fmaxf(hi + hi2 + bc, 0.f);
                    }
                }
            }
        }
    }
}

// ---------------- layer2 (R11/R6 version) ----------------
__global__ __launch_bounds__(256, 2) void layer2_kernel(
    const float* __restrict__ hin, const float* __restrict__ W,
    const float* __restrict__ bias, const float* __restrict__ Mptr,
    float* __restrict__ hout) {
    constexpr int DIN = 300, DOUT = 100, NS = 4;
    constexpr int ROWS = 80;
    constexpr int ROWSP = 82;
    constexpr int DCH = 100;
    constexpr int WST = 105;
    constexpr int SZP = 101;
    extern __shared__ float sm[];
    float* sM  = sm;                       // 400
    float* sb  = sM + 400;                 // 104
    float* shT = sb + 104;                 // DCH*ROWSP = 8200
    float* sWc = shT + DCH * ROWSP;        // DOUT*WST = 10500
    float* sz  = sWc + DOUT * WST;         // ROWS*SZP = 8080

    int tid = threadIdx.x, lane = tid & 31, wy = tid >> 5;
    size_t samp0 = (size_t)blockIdx.x * NS;

    for (int i = tid; i < 400; i += 256) sM[i] = Mptr[i];
    for (int i = tid; i < DOUT; i += 256) sb[i] = bias[i];

    u64 acc2[5][4];
#pragma unroll
    for (int i = 0; i < 5; i++)
#pragma unroll
        for (int k = 0; k < 4; k++) acc2[i][k] = 0ull;

    const u64* aBase = reinterpret_cast<const u64*>(shT);
    int rowHalf = wy * 5;
    const float* ghrow = hin + samp0 * 20 * DIN;

    for (int dc = 0; dc < DIN; dc += DCH) {
        __syncthreads();
        for (int idx = tid; idx < ROWS * DCH; idx += 256) {
            int r = idx / DCH, j = idx - r * DCH;
            shT[j * ROWSP + r] = ghrow[(size_t)r * DIN + dc + j];
        }
        for (int idx = tid; idx < DOUT * DCH; idx += 256) {
            int o = idx / DCH, j = idx - o * DCH;
            sWc[o * WST + j] = W[(size_t)o * DIN + dc + j];
        }
        __syncthreads();
#pragma unroll 2
        for (int j = 0; j < DCH; j++) {
            const u64* ar = aBase + j * (ROWSP / 2) + rowHalf;
            float w0 = sWc[lane * WST + j];
            float w1 = sWc[(lane + 32) * WST + j];
            float w2 = sWc[(lane + 64) * WST + j];
            float w3 = (lane < 4) ? sWc[(lane + 96) * WST + j] : 0.f;
            u64 wp0 = pack2(w0, w0);
            u64 wp1 = pack2(w1, w1);
            u64 wp2 = pack2(w2, w2);
            u64 wp3 = pack2(w3, w3);
#pragma unroll
            for (int i = 0; i < 5; i++) {
                u64 a2 = ar[i];
                acc2[i][0] = fma2(a2, wp0, acc2[i][0]);
                acc2[i][1] = fma2(a2, wp1, acc2[i][1]);
                acc2[i][2] = fma2(a2, wp2, acc2[i][2]);
                acc2[i][3] = fma2(a2, wp3, acc2[i][3]);
            }
        }
    }
    __syncthreads();

#pragma unroll
    for (int k = 0; k < 4; k++) {
        int c = lane + 32 * k;
        if (c < DOUT) {
#pragma unroll
            for (int i = 0; i < 5; i++) {
                float lo, hi;
                unpack2(lo, hi, acc2[i][k]);
                int r0 = wy * 10 + 2 * i;
                sz[r0 * SZP + c]       = lo;
                sz[(r0 + 1) * SZP + c] = hi;
            }
        }
    }
    __syncthreads();

    float Mr[20];
    {
        int v = lane < 20 ? lane : 0;
#pragma unroll
        for (int u = 0; u < 20; u++) Mr[u] = sM[v * 20 + u];
    }
    for (int t = wy; t < NS * DOUT; t += 8) {
        int ss = t / DOUT, c = t - ss * DOUT;
        float* zc = sz + (ss * 20) * SZP + c;
        float a = 0.f;
#pragma unroll
        for (int u = 0; u < 20; u++) a += Mr[u] * zc[u * SZP];
        float h = fmaxf(a + sb[c], 0.f);
        __syncwarp();
        if (lane < 20) zc[lane * SZP] = h;
        __syncwarp();
    }
    __syncthreads();

    float* go = hout + samp0 * 20 * DOUT;
    for (int idx = tid; idx < ROWS * DOUT; idx += 256) {
        int r = idx / DOUT, c = idx - r * DOUT;
        go[idx] = sz[r * SZP + c];
    }
}

// ---------------- final: NS=4, 8-row W4 chunks -> 110KB smem, 2 blocks/SM ----------------
#define W4STR 1005   // mod 32 = 13 -> conflict-free jl-strided reads
__global__ __launch_bounds__(256, 2) void final_kernel(
    const float* __restrict__ hin, const float* __restrict__ W3, const float* __restrict__ b3,
    const float* __restrict__ Mptr, const float* __restrict__ W4, const float* __restrict__ b4,
    const float* __restrict__ W5, const float* __restrict__ b5, float* __restrict__ out) {
    constexpr int DIN = 100, DINP = 101, DOUT = 50, DOUTP = 51;
    constexpr int NS = 4, ROWS = 80, WCH = 64;
    extern __shared__ float sm[];
    float* sM  = sm;                 // 400
    float* sb3 = sM + 400;           // 64
    float* sh  = sb3 + 64;           // 80*101 = 8080
    float* sz  = sh + ROWS * DINP;   // 80*51 = 4080
    float* sW  = sz + ROWS * DOUTP;  // 64*101 = 6464
    float* sW4 = sW + WCH * DINP;    // 8*W4STR = 8040
    float* sh4 = sW4 + 8 * W4STR;    // 4*100 = 400
    float* ph  = sh4 + NS * 100;     // 256
    float* sW5 = ph + 256;           // 300
    float* sb5 = sW5 + 300;          // 4
    float* sb4 = sb5 + 4;            // 100
    // total = 28188 floats = 110.1 KB

    int tid = threadIdx.x;
    size_t samp0 = (size_t)blockIdx.x * NS;

    for (int i = tid; i < 400; i += 256) sM[i] = Mptr[i];
    for (int i = tid; i < DOUT; i += 256) sb3[i] = b3[i];
    for (int i = tid; i < 300; i += 256) sW5[i] = W5[i];
    for (int i = tid; i < 100; i += 256) sb4[i] = b4[i];
    if (tid < 3) sb5[tid] = b5[tid];
    const float* gh = hin + samp0 * 20 * DIN;
    for (int idx = tid; idx < ROWS * DIN; idx += 256) {
        int r = idx / DIN, d = idx - r * DIN;
        sh[r * DINP + d] = gh[idx];
    }
    for (int idx = tid; idx < WCH * DIN; idx += 256) {
        int c = idx / DIN, d = idx - c * DIN;
        sW[c * DINP + d] = (c < DOUT) ? W3[c * DIN + d] : 0.f;
    }
    __syncthreads();

    int lane = tid & 31, wid = tid >> 5;
    float Mr[20];
    {
        int v = lane < 20 ? lane : 0;
#pragma unroll
        for (int u = 0; u < 20; u++) Mr[u] = sM[v * 20 + u];
    }

    // GEMM z = h @ W3^T : 80 rows, 5 rows per ty, strided cols
    int ty = tid >> 4, tx = tid & 15;
    {
        float acc[5][4];
#pragma unroll
        for (int i = 0; i < 5; i++)
#pragma unroll
            for (int k = 0; k < 4; k++) acc[i][k] = 0.f;
        const float* shp = sh + (ty * 5) * DINP;
        const float* sw0 = sW + tx * DINP;
        for (int d = 0; d < DIN; d++) {
            float a[5];
#pragma unroll
            for (int i = 0; i < 5; i++) a[i] = shp[i * DINP + d];
#pragma unroll
            for (int k = 0; k < 4; k++) {
                float w = sw0[k * 16 * DINP + d];
#pragma unroll
                for (int i = 0; i < 5; i++) acc[i][k] += a[i] * w;
            }
        }
#pragma unroll
        for (int k = 0; k < 4; k++) {
            int gc = tx + k * 16;
            if (gc < DOUT) {
#pragma unroll
                for (int i = 0; i < 5; i++)
                    sz[(ty * 5 + i) * DOUTP + gc] = acc[i][k];
            }
        }
    }
    __syncthreads();

    // h3 = relu(M z + b3) in place
    for (int col = wid; col < NS * DOUT; col += 8) {
        int s = col / DOUT, o = col - s * DOUT;
        float* zc = sz + (s * 20) * DOUTP + o;
        float a = 0.f;
#pragma unroll
        for (int u = 0; u < 20; u++) a += Mr[u] * zc[u * DOUTP];
        float h = fmaxf(a + sb3[o], 0.f);
        __syncwarp();
        if (lane < 20) zc[lane * DOUTP] = h;
        __syncwarp();
    }
    __syncthreads();

    // head: h4 = relu(flat @ W4^T + b4). W4 staged 8 rows/chunk; 32 (s,jl)
    // tasks x 8 partial threads (v-quarter x f-half); 32-lane reduction.
    for (int jc = 0; jc < 100; jc += 8) {
        __syncthreads();
        for (int idx = tid; idx < 8000; idx += 256) {
            int rloc = idx >> 10 == 0 ? idx / 1000 : idx / 1000;  // idx/1000
            rloc = idx / 1000;
            int cloc = idx - rloc * 1000;
            int r = jc + rloc;
            sW4[rloc * W4STR + cloc] = (r < 100) ? W4[(size_t)r * 1000 + cloc] : 0.f;
        }
        __syncthreads();
        int task = tid & 31;          // (s, jl)
        int q = tid >> 5;             // 0..7: (v-quarter, f-half)
        int s = task >> 3, jl = task & 7;
        int vq = q >> 1, fh = q & 1;
        const float* zrow = sz + (s * 20) * DOUTP;
        const float* wrow = sW4 + jl * W4STR;
        float p = 0.f;
        int v0 = vq * 5, f0 = fh * 25;
        for (int v = v0; v < v0 + 5; v++) {
            const float* zp = zrow + v * DOUTP + f0;
            const float* wp = wrow + v * 50 + f0;
#pragma unroll 25
            for (int f = 0; f < 25; f++) p += zp[f] * wp[f];
        }
        ph[tid] = p;
        __syncthreads();
        if (tid < 32) {
            int s2 = tid >> 3, jl2 = tid & 7;
            if (jc + jl2 < 100) {
                float hv = sb4[jc + jl2];
#pragma unroll
                for (int q2 = 0; q2 < 8; q2++) hv += ph[tid + 32 * q2];
                sh4[s2 * 100 + jc + jl2] = fmaxf(hv, 0.f);
            }
        }
    }
    __syncthreads();

    // logits + softmax
    if (tid < NS) {
        const float* hp = sh4 + tid * 100;
        float l[3];
#pragma unroll
        for (int c = 0; c < 3; c++) {
            float a = sb5[c];
            for (int j = 0; j < 100; j++) a += hp[j] * sW5[c * 100 + j];
            l[c] = a;
        }
        float mx = fmaxf(l[0], fmaxf(l[1], l[2]));
        float e0 = expf(l[0] - mx), e1 = expf(l[1] - mx), e2 = expf(l[2] - mx);
        float inv = 1.f / (e0 + e1 + e2);
        size_t ob = (samp0 + (size_t)tid) * 3;
        out[ob + 0] = e0 * inv;
        out[ob + 1] = e1 * inv;
        out[ob + 2] = e2 * inv;
    }
}

// ---------------- host ----------------
extern "C" void kernel_launch(void* const* d_in, const int* in_sizes, int n_in,
                              void* d_out, int out_size) {
    const float *x = 0, *W1 = 0, *b1 = 0, *W2 = 0, *b2 = 0, *W3 = 0, *b3 = 0,
                *W4 = 0, *b4 = 0, *W5 = 0, *b5 = 0;
    int idx_x = -1;
    for (int i = 0; i < n_in; i++) if (in_sizes[i] == 41943040) { idx_x = i; break; }
    if (idx_x == 0 || idx_x < 0) {
        x  = (const float*)d_in[0];
        W1 = (const float*)d_in[1];  b1 = (const float*)d_in[2];
        W2 = (const float*)d_in[3];  b2 = (const float*)d_in[4];
        W3 = (const float*)d_in[5];  b3 = (const float*)d_in[6];
        W4 = (const float*)d_in[7];  b4 = (const float*)d_in[8];
        W5 = (const float*)d_in[9];  b5 = (const float*)d_in[10];
    } else {
        int i300_a = -1, i300_b = -1, i100_a = -1, i100_b = -1;
        for (int i = 0; i < n_in; i++) {
            int s = in_sizes[i];
            if (s == 38400)  W1 = (const float*)d_in[i];
            else if (s == 30000) W2 = (const float*)d_in[i];
            else if (s == 5000)  W3 = (const float*)d_in[i];
            else if (s == 100000) W4 = (const float*)d_in[i];
            else if (s == 50)    b3 = (const float*)d_in[i];
            else if (s == 3)     b5 = (const float*)d_in[i];
            else if (s == 41943040) x = (const float*)d_in[i];
            else if (s == 300) { if (i300_a < 0) i300_a = i; else i300_b = i; }
            else if (s == 100) { if (i100_a < 0) i100_a = i; else i100_b = i; }
        }
        W5 = (const float*)d_in[i300_a];  b1 = (const float*)d_in[i300_b];
        b2 = (const float*)d_in[i100_a];  b4 = (const float*)d_in[i100_b];
    }
    float* out = (float*)d_out;

    float *pC = 0, *pM = 0, *ph1 = 0, *ph2 = 0;
    cudaGetSymbolAddress((void**)&pC, g_C);
    cudaGetSymbolAddress((void**)&pM, g_M);
    cudaGetSymbolAddress((void**)&ph1, g_h1);
    cudaGetSymbolAddress((void**)&ph2, g_h2);

    size_t sm_l1  = sizeof(float) * (size_t)(400 + 304 + 128 * 84 + 128 * 133);
    size_t sm_l2  = sizeof(float) * (size_t)(400 + 104 + 100 * 82 + 100 * 105 + 80 * 101);
    size_t sm_k128 = sizeof(float) * (size_t)(80 * 129 + 80 + 4 * 400 + 400);
    size_t sm_k300 = sizeof(float) * (size_t)(80 * 301 + 80 + 4 * 400 + 400);
    size_t sm_k100 = sizeof(float) * (size_t)(80 * 101 + 80 + 4 * 400 + 400);
    size_t sm_fin = sizeof(float) * (size_t)(400 + 64 + 80 * 101 + 80 * 51 +
                                             64 * 101 + 8 * W4STR + 400 + 256 + 300 + 4 + 100);

    cudaFuncSetAttribute(layer1_kernel, cudaFuncAttributeMaxDynamicSharedMemorySize, (int)sm_l1);
    cudaFuncSetAttribute(layer2_kernel, cudaFuncAttributeMaxDynamicSharedMemorySize, (int)sm_l2);
    cudaFuncSetAttribute((knn_kernel<4, 128>), cudaFuncAttributeMaxDynamicSharedMemorySize, (int)sm_k128);
    cudaFuncSetAttribute((knn_kernel<4, 300>), cudaFuncAttributeMaxDynamicSharedMemorySize, (int)sm_k300);
    cudaFuncSetAttribute((knn_kernel<4, 100>), cudaFuncAttributeMaxDynamicSharedMemorySize, (int)sm_k100);
    cudaFuncSetAttribute(final_kernel, cudaFuncAttributeMaxDynamicSharedMemorySize, (int)sm_fin);

    zero_counts_kernel<<<5, 256>>>(pC);
    knn_kernel<4, 128><<<BATCH / 4, 256, sm_k128>>>(x, pC);
    build_M_kernel<<<1, 64>>>(pC, pM);
    layer1_kernel<<<BATCH / 4, 256, sm_l1>>>(x, W1, b1, pM, ph1);
    knn_kernel<4, 300><<<BATCH / 4, 256, sm_k300>>>(ph1, pC + 400);
    build_M_kernel<<<1, 64>>>(pC + 400, pM + 400);
    layer2_kernel<<<BATCH / 4, 256, sm_l2>>>(ph1, W2, b2, pM + 400, ph2);
    knn_kernel<4, 100><<<BATCH / 4, 256, sm_k100>>>(ph2, pC + 800);
    build_M_kernel<<<1, 64>>>(pC + 800, pM + 800);
    final_kernel<<<BATCH / 4, 256, sm_fin>>>(ph2, W3, b3, pM + 800, W4, b4, W5, b5, out);
}

// round 17
// speedup vs baseline: 1.1954x; 1.0798x over previous
#include <cuda_runtime.h>
#include <math.h>

#define BATCH 16384
#define KNN 5

typedef unsigned long long u64;

// ---------------- scratch ----------------
__device__ float g_h1[BATCH * 20 * 300];
__device__ float g_h2[BATCH * 20 * 100];
__device__ float g_C[3 * 400];
__device__ float g_M[3 * 400];

// ---------------- packed f32x2 helpers ----------------
__device__ __forceinline__ u64 pack2(float lo, float hi) {
    u64 r;
    asm("mov.b64 %0, {%1, %2};" : "=l"(r) : "f"(lo), "f"(hi));
    return r;
}
__device__ __forceinline__ void unpack2(float& lo, float& hi, u64 v) {
    asm("mov.b64 {%0, %1}, %2;" : "=f"(lo), "=f"(hi) : "l"(v));
}
__device__ __forceinline__ u64 fma2(u64 a, u64 b, u64 c) {
    u64 d;
    asm("fma.rn.f32x2 %0, %1, %2, %3;" : "=l"(d) : "l"(a), "l"(b), "l"(c));
    return d;
}

// ---------------- tiny kernels ----------------
__global__ void zero_counts_kernel(float* C) {
    int t = blockIdx.x * blockDim.x + threadIdx.x;
    if (t < 1200) C[t] = 0.f;
}

__global__ void build_M_kernel(const float* __restrict__ C, float* __restrict__ M) {
    __shared__ float dinv[20];
    int t = threadIdx.x;
    if (t < 20) {
        float s = 1.f;
#pragma unroll
        for (int u = 0; u < 20; u++) s += C[t * 20 + u];
        dinv[t] = 1.f / sqrtf(s);
    }
    __syncthreads();
    for (int i = t; i < 400; i += blockDim.x) {
        int v = i / 20, u = i % 20;
        float m = dinv[v] * C[i] * dinv[u];
        if (v == u) m += dinv[v] * dinv[v];
        M[i] = m;
    }
}

// ---------------- block-local kNN + count accumulation (scalar, R6) ----------------
template<int NS, int DIM, int STRIDE>
__device__ void knn_accumulate(const float* __restrict__ sh,
                               float* __restrict__ sdq, float* __restrict__ sd2,
                               float* __restrict__ sC, float* __restrict__ gC,
                               int tid) {
    constexpr int ROWS = NS * 20;
    for (int i = tid; i < 400; i += 256) sC[i] = 0.f;
    for (int t = tid; t < ROWS; t += 256) {
        const float* hp = sh + t * STRIDE;
        float s = 0.f;
        for (int d = 0; d < DIM; d++) { float h = hp[d]; s += h * h; }
        sdq[t] = s;
    }
    __syncthreads();
    for (int t = tid; t < NS * 190; t += 256) {
        int s = t / 190, rem = t % 190;
        int i = 0;
        while (rem >= 19 - i) { rem -= 19 - i; i++; }
        int j = i + 1 + rem;
        const float* ha = sh + (s * 20 + i) * STRIDE;
        const float* hb = sh + (s * 20 + j) * STRIDE;
        float dot = 0.f;
        for (int d = 0; d < DIM; d++) dot += ha[d] * hb[d];
        float d2 = sdq[s * 20 + i] + sdq[s * 20 + j] - 2.f * dot;
        sd2[s * 400 + i * 20 + j] = d2;
        sd2[s * 400 + j * 20 + i] = d2;
    }
    __syncthreads();
    for (int t = tid; t < ROWS; t += 256) {
        int s = t / 20, v = t % 20;
        const float* row = sd2 + s * 400 + v * 20;
        float bv[KNN]; int bi[KNN];
#pragma unroll
        for (int k = 0; k < KNN; k++) { bv[k] = 3.4e38f; bi[k] = 99; }
        for (int u = 0; u < 20; u++) {
            if (u == v) continue;
            float d = row[u];
            if (d < bv[KNN - 1]) {
                bv[KNN - 1] = d; bi[KNN - 1] = u;
#pragma unroll
                for (int k = KNN - 1; k > 0; k--) {
                    if (bv[k] < bv[k - 1]) {
                        float tv = bv[k]; bv[k] = bv[k - 1]; bv[k - 1] = tv;
                        int ti = bi[k]; bi[k] = bi[k - 1]; bi[k - 1] = ti;
                    }
                }
            }
        }
#pragma unroll
        for (int k = 0; k < KNN; k++)
            atomicAdd(&sC[bi[k] * 20 + v], 1.f);   // C[nbr][src]
    }
    __syncthreads();
    for (int i = tid; i < 400; i += 256) {
        float c = sC[i];
        if (c != 0.f) atomicAdd(&gC[i], c);
    }
}

// ---------------- standalone kNN kernel (R6: odd stride DIM+1, scalar) ----------------
template<int NS, int DIM>
__global__ __launch_bounds__(256) void knn_kernel(const float* __restrict__ h,
                                                  float* __restrict__ gC) {
    constexpr int DIMP = DIM + 1;
    constexpr int ROWS = NS * 20;
    extern __shared__ float sm[];
    float* sh  = sm;
    float* sdq = sh + ROWS * DIMP;
    float* sd2 = sdq + ROWS;
    float* sC  = sd2 + NS * 400;
    int tid = threadIdx.x;
    size_t samp0 = (size_t)blockIdx.x * NS;
    const float* gx = h + samp0 * 20 * DIM;
    for (int idx = tid; idx < ROWS * DIM; idx += 256) {
        int r = idx / DIM, d = idx - r * DIM;
        sh[r * DIMP + d] = gx[idx];
    }
    __syncthreads();
    knn_accumulate<NS, DIM, DIMP>(sh, sdq, sd2, sC, gC, tid);
}

// ---------------- layer1 (R12 split-K, measured ~822us) ----------------
__global__ __launch_bounds__(256, 2) void layer1_kernel(
    const float* __restrict__ hin, const float* __restrict__ W,
    const float* __restrict__ bias, const float* __restrict__ Mptr,
    float* __restrict__ hout) {
    constexpr int DIN = 128, DOUT = 300, NS = 4;
    constexpr int ROWS = 80;
    constexpr int RP = 84;
    constexpr int WSTR = 133;
    constexpr int WCH = 128;
    extern __shared__ float sm[];
    float* sM  = sm;                      // 400
    float* sb  = sM + 400;                // 304
    float* shT = sb + 304;                // DIN*RP = 10752
    float* sW  = shT + DIN * RP;          // WCH*WSTR = 17024 (reused as scratch)
    u64* scratch = reinterpret_cast<u64*>(sW);

    int tid = threadIdx.x, lane = tid & 31, wy = tid >> 5;
    size_t samp0 = (size_t)blockIdx.x * NS;

    for (int i = tid; i < 400; i += 256) sM[i] = Mptr[i];
    for (int i = tid; i < DOUT; i += 256) sb[i] = bias[i];
    const float* gh = hin + samp0 * 20 * DIN;
    for (int idx = tid; idx < ROWS * DIN; idx += 256) {
        int r = idx >> 7, d = idx & 127;
        shT[d * RP + r] = gh[idx];
    }
    __syncthreads();

    float Mr[20];
    {
        int v = lane < 20 ? lane : 0;
#pragma unroll
        for (int u = 0; u < 20; u++) Mr[u] = sM[v * 20 + u];
    }
    for (int col = wy; col < NS * DIN; col += 8) {
        int s = col >> 7, d = col & 127;
        float* c0 = shT + d * RP + s * 20;
        float a = 0.f;
#pragma unroll
        for (int u = 0; u < 20; u++) a += Mr[u] * c0[u];
        __syncwarp();
        if (lane < 20) c0[lane] = a;
        __syncwarp();
    }
    __syncthreads();

    int s = wy >> 1, dh = wy & 1;
    int dbeg = dh * 64, dend = dbeg + 64;
    float* go = hout + samp0 * 20 * DOUT;

    for (int cb = 0; cb < DOUT; cb += WCH) {
        __syncthreads();
        for (int idx = tid; idx < WCH * DIN; idx += 256) {
            int c = idx >> 7, d = idx & 127;
            int gc = cb + c;
            sW[c * WSTR + d] = (gc < DOUT) ? W[(size_t)gc * DIN + d] : 0.f;
        }
        __syncthreads();

        u64 acc2[10][4];
#pragma unroll
        for (int i = 0; i < 10; i++)
#pragma unroll
            for (int k = 0; k < 4; k++) acc2[i][k] = 0ull;

        const float* wb0 = sW + lane * WSTR;
        const float* wb1 = sW + (lane + 32) * WSTR;
        const float* wb2 = sW + (lane + 64) * WSTR;
        const float* wb3 = sW + (lane + 96) * WSTR;
        for (int d = dbeg; d < dend; d++) {
            const ulonglong2* ap = reinterpret_cast<const ulonglong2*>(shT + d * RP + s * 20);
            ulonglong2 p0 = ap[0], p1 = ap[1], p2 = ap[2], p3 = ap[3], p4 = ap[4];
            u64 a2[10] = {p0.x, p0.y, p1.x, p1.y, p2.x, p2.y, p3.x, p3.y, p4.x, p4.y};
            float w0 = wb0[d], w1 = wb1[d], w2 = wb2[d], w3 = wb3[d];
            u64 wp0 = pack2(w0, w0), wp1 = pack2(w1, w1);
            u64 wp2 = pack2(w2, w2), wp3 = pack2(w3, w3);
#pragma unroll
            for (int i = 0; i < 10; i++) {
                u64 a = a2[i];
                acc2[i][0] = fma2(a, wp0, acc2[i][0]);
                acc2[i][1] = fma2(a, wp1, acc2[i][1]);
                acc2[i][2] = fma2(a, wp2, acc2[i][2]);
                acc2[i][3] = fma2(a, wp3, acc2[i][3]);
            }
        }
        __syncthreads();

        if (dh == 1) {
            u64* dst = scratch + s * 1312 + lane * 41;
#pragma unroll
            for (int i = 0; i < 10; i++)
#pragma unroll
                for (int k = 0; k < 4; k++)
                    dst[i * 4 + k] = acc2[i][k];
        }
        __syncthreads();

        if (dh == 0) {
            const u64* src = scratch + s * 1312 + lane * 41;
#pragma unroll
            for (int k = 0; k < 4; k++) {
                int c = cb + lane + 32 * k;
                if (c < DOUT) {
                    float bc = sb[c];
#pragma unroll
                    for (int i = 0; i < 10; i++) {
                        float lo, hi, lo2, hi2;
                        unpack2(lo, hi, acc2[i][k]);
                        unpack2(lo2, hi2, src[i * 4 + k]);
                        int r0 = s * 20 + 2 * i;
                        go[(size_t)r0 * DOUT + c]       = fmaxf(lo + lo2 + bc, 0.f);
                        go[(size_t)(r0 + 1) * DOUT + c] = fmaxf(hi + hi2 + bc, 0.f);
                    }
                }
            }
        }
    }
}

// ---------------- layer2 (R11/R6 version) ----------------
__global__ __launch_bounds__(256, 2) void layer2_kernel(
    const float* __restrict__ hin, const float* __restrict__ W,
    const float* __restrict__ bias, const float* __restrict__ Mptr,
    float* __restrict__ hout) {
    constexpr int DIN = 300, DOUT = 100, NS = 4;
    constexpr int ROWS = 80;
    constexpr int ROWSP = 82;
    constexpr int DCH = 100;
    constexpr int WST = 105;
    constexpr int SZP = 101;
    extern __shared__ float sm[];
    float* sM  = sm;                       // 400
    float* sb  = sM + 400;                 // 104
    float* shT = sb + 104;                 // DCH*ROWSP = 8200
    float* sWc = shT + DCH * ROWSP;        // DOUT*WST = 10500
    float* sz  = sWc + DOUT * WST;         // ROWS*SZP = 8080

    int tid = threadIdx.x, lane = tid & 31, wy = tid >> 5;
    size_t samp0 = (size_t)blockIdx.x * NS;

    for (int i = tid; i < 400; i += 256) sM[i] = Mptr[i];
    for (int i = tid; i < DOUT; i += 256) sb[i] = bias[i];

    u64 acc2[5][4];
#pragma unroll
    for (int i = 0; i < 5; i++)
#pragma unroll
        for (int k = 0; k < 4; k++) acc2[i][k] = 0ull;

    const u64* aBase = reinterpret_cast<const u64*>(shT);
    int rowHalf = wy * 5;
    const float* ghrow = hin + samp0 * 20 * DIN;

    for (int dc = 0; dc < DIN; dc += DCH) {
        __syncthreads();
        for (int idx = tid; idx < ROWS * DCH; idx += 256) {
            int r = idx / DCH, j = idx - r * DCH;
            shT[j * ROWSP + r] = ghrow[(size_t)r * DIN + dc + j];
        }
        for (int idx = tid; idx < DOUT * DCH; idx += 256) {
            int o = idx / DCH, j = idx - o * DCH;
            sWc[o * WST + j] = W[(size_t)o * DIN + dc + j];
        }
        __syncthreads();
#pragma unroll 2
        for (int j = 0; j < DCH; j++) {
            const u64* ar = aBase + j * (ROWSP / 2) + rowHalf;
            float w0 = sWc[lane * WST + j];
            float w1 = sWc[(lane + 32) * WST + j];
            float w2 = sWc[(lane + 64) * WST + j];
            float w3 = (lane < 4) ? sWc[(lane + 96) * WST + j] : 0.f;
            u64 wp0 = pack2(w0, w0);
            u64 wp1 = pack2(w1, w1);
            u64 wp2 = pack2(w2, w2);
            u64 wp3 = pack2(w3, w3);
#pragma unroll
            for (int i = 0; i < 5; i++) {
                u64 a2 = ar[i];
                acc2[i][0] = fma2(a2, wp0, acc2[i][0]);
                acc2[i][1] = fma2(a2, wp1, acc2[i][1]);
                acc2[i][2] = fma2(a2, wp2, acc2[i][2]);
                acc2[i][3] = fma2(a2, wp3, acc2[i][3]);
            }
        }
    }
    __syncthreads();

#pragma unroll
    for (int k = 0; k < 4; k++) {
        int c = lane + 32 * k;
        if (c < DOUT) {
#pragma unroll
            for (int i = 0; i < 5; i++) {
                float lo, hi;
                unpack2(lo, hi, acc2[i][k]);
                int r0 = wy * 10 + 2 * i;
                sz[r0 * SZP + c]       = lo;
                sz[(r0 + 1) * SZP + c] = hi;
            }
        }
    }
    __syncthreads();

    float Mr[20];
    {
        int v = lane < 20 ? lane : 0;
#pragma unroll
        for (int u = 0; u < 20; u++) Mr[u] = sM[v * 20 + u];
    }
    for (int t = wy; t < NS * DOUT; t += 8) {
        int ss = t / DOUT, c = t - ss * DOUT;
        float* zc = sz + (ss * 20) * SZP + c;
        float a = 0.f;
#pragma unroll
        for (int u = 0; u < 20; u++) a += Mr[u] * zc[u * SZP];
        float h = fmaxf(a + sb[c], 0.f);
        __syncwarp();
        if (lane < 20) zc[lane * SZP] = h;
        __syncwarp();
    }
    __syncthreads();

    float* go = hout + samp0 * 20 * DOUT;
    for (int idx = tid; idx < ROWS * DOUT; idx += 256) {
        int r = idx / DOUT, c = idx - r * DOUT;
        go[idx] = sz[r * SZP + c];
    }
}

// ---------------- final: NS=4, sW4 aliased onto sh, 50-row W3 stage -> 73KB, 3 blocks/SM ----------------
#define W4STR 1005   // mod 32 = 13 -> conflict-free jl-strided reads
__global__ __launch_bounds__(256, 3) void final_kernel(
    const float* __restrict__ hin, const float* __restrict__ W3, const float* __restrict__ b3,
    const float* __restrict__ Mptr, const float* __restrict__ W4, const float* __restrict__ b4,
    const float* __restrict__ W5, const float* __restrict__ b5, float* __restrict__ out) {
    constexpr int DIN = 100, DINP = 101, DOUT = 50, DOUTP = 51;
    constexpr int NS = 4, ROWS = 80;
    extern __shared__ float sm[];
    float* sM  = sm;                 // 400
    float* sb3 = sM + 400;           // 64
    float* sh  = sb3 + 64;           // 80*101 = 8080  (aliased as sW4 after GEMM)
    float* sz  = sh + ROWS * DINP;   // 80*51 = 4080
    float* sW  = sz + ROWS * DOUTP;  // 50*101 = 5050 (+2 pad)
    float* sh4 = sW + 5052;          // 4*100 = 400
    float* ph  = sh4 + NS * 100;     // 256
    float* sW5 = ph + 256;           // 300
    float* sb5 = sW5 + 300;          // 4
    float* sb4 = sb5 + 4;            // 100
    float* sW4 = sh;                 // alias: 8*W4STR = 8040 <= 8080
    // total = 18736 floats = 73.2 KB

    int tid = threadIdx.x;
    size_t samp0 = (size_t)blockIdx.x * NS;

    for (int i = tid; i < 400; i += 256) sM[i] = Mptr[i];
    for (int i = tid; i < DOUT; i += 256) sb3[i] = b3[i];
    for (int i = tid; i < 300; i += 256) sW5[i] = W5[i];
    for (int i = tid; i < 100; i += 256) sb4[i] = b4[i];
    if (tid < 3) sb5[tid] = b5[tid];
    const float* gh = hin + samp0 * 20 * DIN;
    for (int idx = tid; idx < ROWS * DIN; idx += 256) {
        int r = idx / DIN, d = idx - r * DIN;
        sh[r * DINP + d] = gh[idx];
    }
    for (int idx = tid; idx < DOUT * DIN; idx += 256) {
        int c = idx / DIN, d = idx - c * DIN;
        sW[c * DINP + d] = W3[idx];
    }
    __syncthreads();

    int lane = tid & 31, wid = tid >> 5;
    float Mr[20];
    {
        int v = lane < 20 ? lane : 0;
#pragma unroll
        for (int u = 0; u < 20; u++) Mr[u] = sM[v * 20 + u];
    }

    // GEMM z = h @ W3^T : 80 rows, 5 rows per ty, strided cols.
    // Col slots gc = tx + 16k for k<4 reach 63; rows >= 50 clamp their read
    // pointer to row 49 (results discarded by the gc<DOUT write guard).
    int ty = tid >> 4, tx = tid & 15;
    {
        float acc[5][4];
#pragma unroll
        for (int i = 0; i < 5; i++)
#pragma unroll
            for (int k = 0; k < 4; k++) acc[i][k] = 0.f;
        const float* shp = sh + (ty * 5) * DINP;
        const float* swp[4];
#pragma unroll
        for (int k = 0; k < 4; k++) {
            int gc = tx + k * 16;
            swp[k] = sW + (gc < DOUT ? gc : DOUT - 1) * DINP;
        }
        for (int d = 0; d < DIN; d++) {
            float a[5];
#pragma unroll
            for (int i = 0; i < 5; i++) a[i] = shp[i * DINP + d];
#pragma unroll
            for (int k = 0; k < 4; k++) {
                float w = swp[k][d];
#pragma unroll
                for (int i = 0; i < 5; i++) acc[i][k] += a[i] * w;
            }
        }
#pragma unroll
        for (int k = 0; k < 4; k++) {
            int gc = tx + k * 16;
            if (gc < DOUT) {
#pragma unroll
                for (int i = 0; i < 5; i++)
                    sz[(ty * 5 + i) * DOUTP + gc] = acc[i][k];
            }
        }
    }
    __syncthreads();

    // h3 = relu(M z + b3) in place
    for (int col = wid; col < NS * DOUT; col += 8) {
        int s = col / DOUT, o = col - s * DOUT;
        float* zc = sz + (s * 20) * DOUTP + o;
        float a = 0.f;
#pragma unroll
        for (int u = 0; u < 20; u++) a += Mr[u] * zc[u * DOUTP];
        float h = fmaxf(a + sb3[o], 0.f);
        __syncwarp();
        if (lane < 20) zc[lane * DOUTP] = h;
        __syncwarp();
    }
    __syncthreads();

    // head: h4 = relu(flat @ W4^T + b4). W4 staged 8 rows/chunk into the
    // dead sh buffer; 32 (s,jl) tasks x 8 partial threads; 32-lane reduce.
    for (int jc = 0; jc < 100; jc += 8) {
        __syncthreads();
        for (int idx = tid; idx < 8000; idx += 256) {
            int rloc = idx / 1000;
            int cloc = idx - rloc * 1000;
            int r = jc + rloc;
            sW4[rloc * W4STR + cloc] = (r < 100) ? W4[(size_t)r * 1000 + cloc] : 0.f;
        }
        __syncthreads();
        int task = tid & 31;          // (s, jl)
        int q = tid >> 5;             // 0..7: (v-quarter, f-half)
        int s = task >> 3, jl = task & 7;
        int vq = q >> 1, fh = q & 1;
        const float* zrow = sz + (s * 20) * DOUTP;
        const float* wrow = sW4 + jl * W4STR;
        float p = 0.f;
        int v0 = vq * 5, f0 = fh * 25;
        for (int v = v0; v < v0 + 5; v++) {
            const float* zp = zrow + v * DOUTP + f0;
            const float* wp = wrow + v * 50 + f0;
#pragma unroll 25
            for (int f = 0; f < 25; f++) p += zp[f] * wp[f];
        }
        ph[tid] = p;
        __syncthreads();
        if (tid < 32) {
            int s2 = tid >> 3, jl2 = tid & 7;
            if (jc + jl2 < 100) {
                float hv = sb4[jc + jl2];
#pragma unroll
                for (int q2 = 0; q2 < 8; q2++) hv += ph[tid + 32 * q2];
                sh4[s2 * 100 + jc + jl2] = fmaxf(hv, 0.f);
            }
        }
    }
    __syncthreads();

    // logits + softmax
    if (tid < NS) {
        const float* hp = sh4 + tid * 100;
        float l[3];
#pragma unroll
        for (int c = 0; c < 3; c++) {
            float a = sb5[c];
            for (int j = 0; j < 100; j++) a += hp[j] * sW5[c * 100 + j];
            l[c] = a;
        }
        float mx = fmaxf(l[0], fmaxf(l[1], l[2]));
        float e0 = expf(l[0] - mx), e1 = expf(l[1] - mx), e2 = expf(l[2] - mx);
        float inv = 1.f / (e0 + e1 + e2);
        size_t ob = (samp0 + (size_t)tid) * 3;
        out[ob + 0] = e0 * inv;
        out[ob + 1] = e1 * inv;
        out[ob + 2] = e2 * inv;
    }
}

// ---------------- host ----------------
extern "C" void kernel_launch(void* const* d_in, const int* in_sizes, int n_in,
                              void* d_out, int out_size) {
    const float *x = 0, *W1 = 0, *b1 = 0, *W2 = 0, *b2 = 0, *W3 = 0, *b3 = 0,
                *W4 = 0, *b4 = 0, *W5 = 0, *b5 = 0;
    int idx_x = -1;
    for (int i = 0; i < n_in; i++) if (in_sizes[i] == 41943040) { idx_x = i; break; }
    if (idx_x == 0 || idx_x < 0) {
        x  = (const float*)d_in[0];
        W1 = (const float*)d_in[1];  b1 = (const float*)d_in[2];
        W2 = (const float*)d_in[3];  b2 = (const float*)d_in[4];
        W3 = (const float*)d_in[5];  b3 = (const float*)d_in[6];
        W4 = (const float*)d_in[7];  b4 = (const float*)d_in[8];
        W5 = (const float*)d_in[9];  b5 = (const float*)d_in[10];
    } else {
        int i300_a = -1, i300_b = -1, i100_a = -1, i100_b = -1;
        for (int i = 0; i < n_in; i++) {
            int s = in_sizes[i];
            if (s == 38400)  W1 = (const float*)d_in[i];
            else if (s == 30000) W2 = (const float*)d_in[i];
            else if (s == 5000)  W3 = (const float*)d_in[i];
            else if (s == 100000) W4 = (const float*)d_in[i];
            else if (s == 50)    b3 = (const float*)d_in[i];
            else if (s == 3)     b5 = (const float*)d_in[i];
            else if (s == 41943040) x = (const float*)d_in[i];
            else if (s == 300) { if (i300_a < 0) i300_a = i; else i300_b = i; }
            else if (s == 100) { if (i100_a < 0) i100_a = i; else i100_b = i; }
        }
        W5 = (const float*)d_in[i300_a];  b1 = (const float*)d_in[i300_b];
        b2 = (const float*)d_in[i100_a];  b4 = (const float*)d_in[i100_b];
    }
    float* out = (float*)d_out;

    float *pC = 0, *pM = 0, *ph1 = 0, *ph2 = 0;
    cudaGetSymbolAddress((void**)&pC, g_C);
    cudaGetSymbolAddress((void**)&pM, g_M);
    cudaGetSymbolAddress((void**)&ph1, g_h1);
    cudaGetSymbolAddress((void**)&ph2, g_h2);

    size_t sm_l1  = sizeof(float) * (size_t)(400 + 304 + 128 * 84 + 128 * 133);
    size_t sm_l2  = sizeof(float) * (size_t)(400 + 104 + 100 * 82 + 100 * 105 + 80 * 101);
    size_t sm_k128 = sizeof(float) * (size_t)(80 * 129 + 80 + 4 * 400 + 400);
    size_t sm_k300 = sizeof(float) * (size_t)(40 * 301 + 40 + 2 * 400 + 400);
    size_t sm_k100 = sizeof(float) * (size_t)(80 * 101 + 80 + 4 * 400 + 400);
    size_t sm_fin = sizeof(float) * (size_t)(400 + 64 + 80 * 101 + 80 * 51 +
                                             5052 + 400 + 256 + 300 + 4 + 100);

    cudaFuncSetAttribute(layer1_kernel, cudaFuncAttributeMaxDynamicSharedMemorySize, (int)sm_l1);
    cudaFuncSetAttribute(layer2_kernel, cudaFuncAttributeMaxDynamicSharedMemorySize, (int)sm_l2);
    cudaFuncSetAttribute((knn_kernel<4, 128>), cudaFuncAttributeMaxDynamicSharedMemorySize, (int)sm_k128);
    cudaFuncSetAttribute((knn_kernel<2, 300>), cudaFuncAttributeMaxDynamicSharedMemorySize, (int)sm_k300);
    cudaFuncSetAttribute((knn_kernel<4, 100>), cudaFuncAttributeMaxDynamicSharedMemorySize, (int)sm_k100);
    cudaFuncSetAttribute(final_kernel, cudaFuncAttributeMaxDynamicSharedMemorySize, (int)sm_fin);

    zero_counts_kernel<<<5, 256>>>(pC);
    knn_kernel<4, 128><<<BATCH / 4, 256, sm_k128>>>(x, pC);
    build_M_kernel<<<1, 64>>>(pC, pM);
    layer1_kernel<<<BATCH / 4, 256, sm_l1>>>(x, W1, b1, pM, ph1);
    knn_kernel<2, 300><<<BATCH / 2, 256, sm_k300>>>(ph1, pC + 400);
    build_M_kernel<<<1, 64>>>(pC + 400, pM + 400);
    layer2_kernel<<<BATCH / 4, 256, sm_l2>>>(ph1, W2, b2, pM + 400, ph2);
    knn_kernel<4, 100><<<BATCH / 4, 256, sm_k100>>>(ph2, pC + 800);
    build_M_kernel<<<1, 64>>>(pC + 800, pM + 800);
    final_kernel<<<BATCH / 4, 256, sm_fin>>>(ph2, W3, b3, pM + 800, W4, b4, W5, b5, out);
}